// round 14
// baseline (speedup 1.0000x reference)
#include <cuda_runtime.h>
#include <cuda_fp16.h>
#include <cstdint>

// ---------------------------------------------------------------------------
// DeepFM on GB300 (compute_103 -> HMMA mma.sync path):
//   prepare (gather[unroll4] + 3x weight transpose merged, 1 launch)
//   -> gemm0 (CTA 128x256 f16-acc, 2 CTAs/SM, BK=64, NST=2, K0PAD=896)
//   -> gemm12_head (M=128, phase1 NST=4, f16-acc, fused head)   [R13 config]
// ---------------------------------------------------------------------------

#define B_ROWS 16384
#define NFIELD 26
#define VOCAB  100000
#define EDIM   32
#define NDENSE 13
#define K0PAD  896   // 845 padded to multiple of 64

__device__ __half g_h0[(size_t)B_ROWS * K0PAD];
__device__ __half g_h1[(size_t)B_ROWS * 1024];
__device__ float  g_logit0[B_ROWS];
__device__ __half g_W0t[(size_t)1024 * K0PAD];  // [N,K] K-major fp16
__device__ __half g_W1t[(size_t)512 * 1024];
__device__ __half g_W2t[(size_t)256 * 512];

// ---------------------------------------------------------------------------
__device__ __forceinline__ uint32_t smem_to_u32(const void* p) {
    uint32_t a;
    asm("{ .reg .u64 t; cvta.to.shared.u64 t, %1; cvt.u32.u64 %0, t; }"
        : "=r"(a) : "l"(p));
    return a;
}
__device__ __forceinline__ void cp_async16(uint32_t dst, const void* src) {
    asm volatile("cp.async.cg.shared.global [%0], [%1], 16;"
                 :: "r"(dst), "l"(src) : "memory");
}
__device__ __forceinline__ void cp_async16_ca(uint32_t dst, const void* src) {
    asm volatile("cp.async.ca.shared.global [%0], [%1], 16;"
                 :: "r"(dst), "l"(src) : "memory");
}
__device__ __forceinline__ void cp_commit() {
    asm volatile("cp.async.commit_group;" ::: "memory");
}
template <int N>
__device__ __forceinline__ void cp_wait() {
    asm volatile("cp.async.wait_group %0;" :: "n"(N) : "memory");
}
__device__ __forceinline__ void ldsm_x4(uint32_t* r, uint32_t addr) {
    asm volatile("ldmatrix.sync.aligned.m8n8.x4.shared.b16 {%0,%1,%2,%3}, [%4];"
                 : "=r"(r[0]), "=r"(r[1]), "=r"(r[2]), "=r"(r[3]) : "r"(addr));
}
__device__ __forceinline__ void mma_f16(uint32_t* c, const uint32_t* a,
                                        uint32_t b0, uint32_t b1) {
    asm volatile(
        "mma.sync.aligned.m16n8k16.row.col.f16.f16.f16.f16 "
        "{%0,%1}, {%2,%3,%4,%5}, {%6,%7}, {%0,%1};"
        : "+r"(c[0]), "+r"(c[1])
        : "r"(a[0]), "r"(a[1]), "r"(a[2]), "r"(a[3]), "r"(b0), "r"(b1));
}

// ---------------------------------------------------------------------------
// Merged prepare kernel: block-range dispatch.
#define NB_P0 (28 * 32)                       // 896 K-cols / 32
#define NB_P1 (32 * 16)
#define NB_P2 (16 * 8)
#define NB_PREP (NB_P0 + NB_P1 + NB_P2)       // 1536
#define NB_GATHER (B_ROWS / 8)                // 2048
#define NB_TOTAL (NB_PREP + NB_GATHER)        // 3584

__device__ __forceinline__ void transpose_tile(
    const float* __restrict__ W, __half* __restrict__ out,
    int N, int K, int KP, int bk, int bn, float (*sm)[33])
{
    const int tx = threadIdx.x & 31, ty = threadIdx.x >> 5;
    #pragma unroll
    for (int i = 0; i < 4; ++i) {
        int k = bk + ty + 8 * i;
        sm[ty + 8 * i][tx] = (k < K) ? __ldg(W + (size_t)k * N + bn + tx) : 0.0f;
    }
    __syncthreads();
    #pragma unroll
    for (int i = 0; i < 4; ++i) {
        int n = bn + ty + 8 * i;
        out[(size_t)n * KP + bk + tx] = __float2half(sm[tx][ty + 8 * i]);
    }
}

__global__ __launch_bounds__(256)
void prepare_kernel(const int* __restrict__ xs,
                    const float* __restrict__ xd,
                    const float* __restrict__ emb,
                    const float* __restrict__ lin,
                    const float* __restrict__ W0,
                    const float* __restrict__ W1,
                    const float* __restrict__ W2) {
    __shared__ float sm[32][33];
    const int blk = blockIdx.x;

    if (blk < NB_P0) {
        transpose_tile(W0, g_W0t, 1024, 845, K0PAD,
                       (blk % 28) * 32, (blk / 28) * 32, sm);
        return;
    }
    if (blk < NB_P0 + NB_P1) {
        const int b = blk - NB_P0;
        transpose_tile(W1, g_W1t, 512, 1024, 1024,
                       (b % 32) * 32, (b / 32) * 32, sm);
        return;
    }
    if (blk < NB_PREP) {
        const int b = blk - NB_P0 - NB_P1;
        transpose_tile(W2, g_W2t, 256, 512, 512,
                       (b % 16) * 32, (b / 16) * 32, sm);
        return;
    }

    // ---- gather: 8 warps per block, one batch row per warp, unroll 4 ----
    const int wid  = threadIdx.x >> 5;
    const int lane = threadIdx.x & 31;
    const int b    = (blk - NB_PREP) * 8 + wid;

    int   idx_l = 0;
    float linv  = 0.0f;
    if (lane < NFIELD) {
        idx_l = xs[b * NFIELD + lane];
        linv  = __ldg(lin + (size_t)lane * VOCAB + idx_l);
    }

    float s = 0.0f, ss = 0.0f;
    __half* h0row = g_h0 + (size_t)b * K0PAD;

    #pragma unroll
    for (int f0 = 0; f0 < 24; f0 += 4) {
        float v[4];
        #pragma unroll
        for (int u = 0; u < 4; ++u) {
            int idx = __shfl_sync(0xffffffffu, idx_l, f0 + u);
            v[u] = __ldg(emb + ((size_t)(f0 + u) * VOCAB + idx) * EDIM + lane);
        }
        #pragma unroll
        for (int u = 0; u < 4; ++u) {
            s  += v[u];
            ss += v[u] * v[u];
            h0row[(f0 + u) * EDIM + lane] = __float2half(v[u]);
        }
    }
    {
        float v[2];
        #pragma unroll
        for (int u = 0; u < 2; ++u) {
            int idx = __shfl_sync(0xffffffffu, idx_l, 24 + u);
            v[u] = __ldg(emb + ((size_t)(24 + u) * VOCAB + idx) * EDIM + lane);
        }
        #pragma unroll
        for (int u = 0; u < 2; ++u) {
            s  += v[u];
            ss += v[u] * v[u];
            h0row[(24 + u) * EDIM + lane] = __float2half(v[u]);
        }
    }
    // cols 832..863: dense + pad; cols 864..895: pad zeros
    h0row[NFIELD * EDIM + lane] =
        __float2half((lane < NDENSE) ? xd[b * NDENSE + lane] : 0.0f);
    h0row[NFIELD * EDIM + 32 + lane] = __float2half(0.0f);

    float s2 = s * s;
    #pragma unroll
    for (int o = 16; o; o >>= 1) {
        ss   += __shfl_xor_sync(0xffffffffu, ss,   o);
        s2   += __shfl_xor_sync(0xffffffffu, s2,   o);
        linv += __shfl_xor_sync(0xffffffffu, linv, o);
    }
    if (lane == 0) g_logit0[b] = linv + 0.5f * (s2 - ss);
}

// ---------------------------------------------------------------------------
#define BK       32                        // for the fused kernel
#define AROWB    80                        // fused: 64 halves + 16B pad

// ===== gemm0: CTA 128x256, 8 warps (2M x 4N), warp 64x64, f16 acc,
//       2 CTAs/SM, BK=64, NST=2, grid (128, 4) x-fast on M.
#define BK0      64
#define AROW0    144                       // bytes/row: 128 + 16 pad
#define AT0      (128 * AROW0)             // 18432
#define BT0      (256 * AROW0)             // 36864
#define ST0      (AT0 + BT0)               // 55296
#define NST0     2
#define GEMM0_SMEM (NST0 * ST0)            // 110592

__global__ __launch_bounds__(256, 2)
void gemm_mma0(const float* __restrict__ bias) {
    extern __shared__ char smem[];
    const uint32_t sbase = smem_to_u32(smem);
    const int tid = threadIdx.x;
    const int warp = tid >> 5, lane = tid & 31;
    const int wm = (warp & 1) * 64, wn = (warp >> 1) * 64;
    const int bm = blockIdx.x * 128, bn = blockIdx.y * 256;   // x = M (fast)
    const int KIT = K0PAD / BK0;           // 14

    const __half* A  = g_h0;
    const __half* Bw = g_W0t + (size_t)bn * K0PAD;

    auto issue = [&](int it) {
        if (it < KIT) {
            const int k0 = it * BK0;
            const uint32_t st = sbase + (it & 1) * ST0;
            // A: 128 rows x 8 segs = 1024 chunks, 4/thread
            #pragma unroll
            for (int q = 0; q < 4; ++q) {
                const int v = tid + 256 * q;
                const int row = v >> 3, seg = v & 7;
                cp_async16(st + row * AROW0 + seg * 16,
                           A + (size_t)(bm + row) * K0PAD + k0 + seg * 8);
            }
            // B: 256 rows x 8 segs = 2048 chunks, 8/thread (.ca: shared tile)
            const uint32_t sb = st + AT0;
            #pragma unroll
            for (int q = 0; q < 8; ++q) {
                const int v = tid + 256 * q;
                const int row = v >> 3, seg = v & 7;
                cp_async16_ca(sb + row * AROW0 + seg * 16,
                              Bw + (size_t)row * K0PAD + k0 + seg * 8);
            }
        }
        cp_commit();
    };

    issue(0);

    uint32_t c[4][8][2];
    #pragma unroll
    for (int i = 0; i < 4; ++i)
        #pragma unroll
        for (int j = 0; j < 8; ++j) { c[i][j][0] = 0u; c[i][j][1] = 0u; }

    const int a_row  = wm + (lane & 15);
    const int a_koff = (lane >> 4) * 8;
    const int b_row  = wn + (lane & 7) + ((lane >> 4) << 3);
    const int b_koff = (lane & 8);

    for (int i = 0; i < KIT; ++i) {
        cp_wait<0>();
        __syncthreads();
        issue(i + 1);   // other buffer; its compute finished before the barrier

        const uint32_t sa = sbase + (i & 1) * ST0;
        const uint32_t sb = sa + AT0;

        #pragma unroll
        for (int kk = 0; kk < 4; ++kk) {
            uint32_t a[4][4], b[4][4];
            #pragma unroll
            for (int mt = 0; mt < 4; ++mt)
                ldsm_x4(a[mt], sa + (a_row + mt * 16) * AROW0 + (kk * 16 + a_koff) * 2);
            #pragma unroll
            for (int nt = 0; nt < 4; ++nt)
                ldsm_x4(b[nt], sb + (b_row + nt * 16) * AROW0 + (kk * 16 + b_koff) * 2);
            #pragma unroll
            for (int mt = 0; mt < 4; ++mt)
                #pragma unroll
                for (int nt = 0; nt < 4; ++nt) {
                    mma_f16(c[mt][2 * nt],     a[mt], b[nt][0], b[nt][1]);
                    mma_f16(c[mt][2 * nt + 1], a[mt], b[nt][2], b[nt][3]);
                }
        }
    }

    const __half2 z2 = __float2half2_rn(0.0f);
    #pragma unroll
    for (int mt = 0; mt < 4; ++mt) {
        const size_t r0 = (size_t)bm + wm + mt * 16 + (lane >> 2);
        #pragma unroll
        for (int j = 0; j < 8; ++j) {
            const int col = bn + wn + j * 8 + 2 * (lane & 3);
            const float2 bf = *reinterpret_cast<const float2*>(bias + col);
            const __half2 bb = __floats2half2_rn(bf.x, bf.y);
            __half2 lo = *reinterpret_cast<__half2*>(&c[mt][j][0]);
            __half2 hi = *reinterpret_cast<__half2*>(&c[mt][j][1]);
            lo = __hmax2(__hadd2(lo, bb), z2);
            hi = __hmax2(__hadd2(hi, bb), z2);
            *reinterpret_cast<__half2*>(g_h1 + r0 * 1024 + col)       = lo;
            *reinterpret_cast<__half2*>(g_h1 + (r0 + 8) * 1024 + col) = hi;
        }
    }
}

// ---------------------------------------------------------------------------
// Fused layers 1+2+head (R13 config). Grid = 128 CTAs x 256 threads.
#define AT1      (128 * AROWB)             // 10240
#define BT1      (512 * AROWB)             // 40960
#define ST1      (AT1 + BT1)               // 51200
#define NST1     4
#define PIPE1    (NST1 * ST1)              // 204800

#define H2PITCH  520                       // halves (512 + 8 pad)
#define H2BYTES  (128 * H2PITCH * 2)       // 133120
#define P2OFF    H2BYTES
#define BT2      (256 * AROWB)             // 20480
#define NST2     3
#define FUSE_SMEM 204800
#define H3PITCH  264

__global__ __launch_bounds__(256, 1)
void gemm12_head(const float* __restrict__ b1,
                 const float* __restrict__ b2,
                 const float* __restrict__ Wout,
                 const float* __restrict__ bout,
                 float* __restrict__ out) {
    extern __shared__ char smem[];
    const uint32_t sbase = smem_to_u32(smem);
    __half* s_h2 = reinterpret_cast<__half*>(smem);
    __half* s_h3 = reinterpret_cast<__half*>(smem);

    const int tid = threadIdx.x;
    const int warp = tid >> 5, lane = tid & 31;
    const int bm = blockIdx.x * 128;
    const __half2 z2 = __float2half2_rn(0.0f);

    // ---- Phase 1: layer 1 (K=1024, N=512), warp 64x128, f16 acc ----
    {
        const int wm = (warp & 1) * 64, wn = (warp >> 1) * 128;
        const int KIT = 1024 / BK;   // 32
        const int row0 = tid >> 2, seg = tid & 3;

        auto issue = [&](int it) {
            if (it < KIT) {
                const int k0 = it * BK;
                const uint32_t st = sbase + (it % NST1) * ST1;
                cp_async16(st + row0 * AROWB + seg * 16,
                           g_h1 + (size_t)(bm + row0) * 1024 + k0 + seg * 8);
                cp_async16(st + (row0 + 64) * AROWB + seg * 16,
                           g_h1 + (size_t)(bm + row0 + 64) * 1024 + k0 + seg * 8);
                const uint32_t sb = st + AT1;
                #pragma unroll
                for (int j = 0; j < 8; ++j)
                    cp_async16(sb + (row0 + 64 * j) * AROWB + seg * 16,
                               g_W1t + (size_t)(row0 + 64 * j) * 1024 + k0 + seg * 8);
            }
            cp_commit();
        };

        #pragma unroll
        for (int s = 0; s < NST1 - 1; ++s) issue(s);

        uint32_t c[4][16][2];
        #pragma unroll
        for (int i = 0; i < 4; ++i)
            #pragma unroll
            for (int j = 0; j < 16; ++j) { c[i][j][0] = 0u; c[i][j][1] = 0u; }

        const int a_row  = wm + (lane & 15);
        const int a_koff = (lane >> 4) * 8;
        const int b_row  = wn + (lane & 7) + ((lane >> 4) << 3);
        const int b_koff = (lane & 8);

        for (int i = 0; i < KIT; ++i) {
            cp_wait<NST1 - 2>();
            __syncthreads();
            issue(i + NST1 - 1);

            const uint32_t sa = sbase + (i % NST1) * ST1;
            const uint32_t sb = sa + AT1;

            #pragma unroll
            for (int kk = 0; kk < 2; ++kk) {
                uint32_t a[4][4], b[8][4];
                #pragma unroll
                for (int mt = 0; mt < 4; ++mt)
                    ldsm_x4(a[mt], sa + (a_row + mt * 16) * AROWB + (kk * 16 + a_koff) * 2);
                #pragma unroll
                for (int nt = 0; nt < 8; ++nt)
                    ldsm_x4(b[nt], sb + (b_row + nt * 16) * AROWB + (kk * 16 + b_koff) * 2);
                #pragma unroll
                for (int mt = 0; mt < 4; ++mt)
                    #pragma unroll
                    for (int nt = 0; nt < 8; ++nt) {
                        mma_f16(c[mt][2 * nt],     a[mt], b[nt][0], b[nt][1]);
                        mma_f16(c[mt][2 * nt + 1], a[mt], b[nt][2], b[nt][3]);
                    }
            }
        }
        __syncthreads();   // pipeline dead; safe to overwrite with h2

        #pragma unroll
        for (int mt = 0; mt < 4; ++mt) {
            const int r0 = wm + mt * 16 + (lane >> 2);
            #pragma unroll
            for (int nt = 0; nt < 16; ++nt) {
                const int col = wn + nt * 8 + 2 * (lane & 3);
                const float2 bf = *reinterpret_cast<const float2*>(b1 + col);
                const __half2 bb = __floats2half2_rn(bf.x, bf.y);
                __half2 lo = *reinterpret_cast<__half2*>(&c[mt][nt][0]);
                __half2 hi = *reinterpret_cast<__half2*>(&c[mt][nt][1]);
                lo = __hmax2(__hadd2(lo, bb), z2);
                hi = __hmax2(__hadd2(hi, bb), z2);
                *reinterpret_cast<__half2*>(s_h2 + r0 * H2PITCH + col)       = lo;
                *reinterpret_cast<__half2*>(s_h2 + (r0 + 8) * H2PITCH + col) = hi;
            }
        }
    }
    __syncthreads();

    // ---- Phase 2: layer 2 (K=512, N=256), warp 64x64, f16 acc ----
    uint32_t c2[4][8][2];
    {
        const int wm = (warp & 1) * 64, wn = (warp >> 1) * 64;
        const int KIT = 512 / BK;   // 16
        const int row0 = tid >> 2, seg = tid & 3;

        auto issueB = [&](int it) {
            if (it < KIT) {
                const int k0 = it * BK;
                const uint32_t st = sbase + P2OFF + (it % NST2) * BT2;
                #pragma unroll
                for (int j = 0; j < 4; ++j)
                    cp_async16(st + (row0 + 64 * j) * AROWB + seg * 16,
                               g_W2t + (size_t)(row0 + 64 * j) * 512 + k0 + seg * 8);
            }
            cp_commit();
        };
        #pragma unroll
        for (int s = 0; s < NST2 - 1; ++s) issueB(s);

        #pragma unroll
        for (int i = 0; i < 4; ++i)
            #pragma unroll
            for (int j = 0; j < 8; ++j) { c2[i][j][0] = 0u; c2[i][j][1] = 0u; }

        const int a_row  = wm + (lane & 15);
        const int a_koff = (lane >> 4) * 8;
        const int b_row  = wn + (lane & 7) + ((lane >> 4) << 3);
        const int b_koff = (lane & 8);

        for (int i = 0; i < KIT; ++i) {
            cp_wait<NST2 - 2>();
            __syncthreads();
            issueB(i + NST2 - 1);

            const uint32_t sb = sbase + P2OFF + (i % NST2) * BT2;

            #pragma unroll
            for (int kk = 0; kk < 2; ++kk) {
                uint32_t a[4][4], b[4][4];
                #pragma unroll
                for (int mt = 0; mt < 4; ++mt)
                    ldsm_x4(a[mt], sbase + (a_row + mt * 16) * (H2PITCH * 2)
                                       + (i * 32 + kk * 16 + a_koff) * 2);
                #pragma unroll
                for (int nt = 0; nt < 4; ++nt)
                    ldsm_x4(b[nt], sb + (b_row + nt * 16) * AROWB + (kk * 16 + b_koff) * 2);
                #pragma unroll
                for (int mt = 0; mt < 4; ++mt)
                    #pragma unroll
                    for (int nt = 0; nt < 4; ++nt) {
                        mma_f16(c2[mt][2 * nt],     a[mt], b[nt][0], b[nt][1]);
                        mma_f16(c2[mt][2 * nt + 1], a[mt], b[nt][2], b[nt][3]);
                    }
            }
        }
    }
    __syncthreads();   // h2 dead; reuse offset 0 for h3

    // ---- Phase 3: h3 -> smem, head ----
    {
        const int wm = (warp & 1) * 64, wn = (warp >> 1) * 64;
        #pragma unroll
        for (int mt = 0; mt < 4; ++mt) {
            const int r0 = wm + mt * 16 + (lane >> 2);
            #pragma unroll
            for (int j = 0; j < 8; ++j) {
                const int col = wn + j * 8 + 2 * (lane & 3);
                const float2 bf = *reinterpret_cast<const float2*>(b2 + col);
                const __half2 bb = __floats2half2_rn(bf.x, bf.y);
                __half2 lo = *reinterpret_cast<__half2*>(&c2[mt][j][0]);
                __half2 hi = *reinterpret_cast<__half2*>(&c2[mt][j][1]);
                lo = __hmax2(__hadd2(lo, bb), z2);
                hi = __hmax2(__hadd2(hi, bb), z2);
                *reinterpret_cast<__half2*>(s_h3 + r0 * H3PITCH + col)       = lo;
                *reinterpret_cast<__half2*>(s_h3 + (r0 + 8) * H3PITCH + col) = hi;
            }
        }
    }
    __syncthreads();

    float wreg[8];
    #pragma unroll
    for (int j = 0; j < 8; ++j) wreg[j] = __ldg(Wout + j * 32 + lane);
    const float bo = __ldg(bout);

    #pragma unroll 1
    for (int t = 0; t < 16; ++t) {
        const int row = warp * 16 + t;
        float acc = 0.0f;
        #pragma unroll
        for (int j = 0; j < 8; ++j)
            acc += __half2float(s_h3[row * H3PITCH + j * 32 + lane]) * wreg[j];
        #pragma unroll
        for (int o = 16; o; o >>= 1) acc += __shfl_xor_sync(0xffffffffu, acc, o);
        if (lane == 0) {
            float logit = acc + bo + g_logit0[bm + row];
            out[bm + row] = 1.0f / (1.0f + expf(-logit));
        }
    }
}

// ---------------------------------------------------------------------------
extern "C" void kernel_launch(void* const* d_in, const int* in_sizes, int n_in,
                              void* d_out, int out_size) {
    const int*   xs   = (const int*)  d_in[0];
    const float* xd   = (const float*)d_in[1];
    const float* emb  = (const float*)d_in[2];
    const float* lin  = (const float*)d_in[3];
    const float* W0   = (const float*)d_in[4];
    const float* b0   = (const float*)d_in[5];
    const float* W1   = (const float*)d_in[6];
    const float* b1   = (const float*)d_in[7];
    const float* W2   = (const float*)d_in[8];
    const float* b2   = (const float*)d_in[9];
    const float* Wout = (const float*)d_in[10];
    const float* bout = (const float*)d_in[11];
    float* out = (float*)d_out;

    static bool attr_done = false;
    if (!attr_done) {
        cudaFuncSetAttribute(gemm_mma0,
                             cudaFuncAttributeMaxDynamicSharedMemorySize, GEMM0_SMEM);
        cudaFuncSetAttribute(gemm12_head,
                             cudaFuncAttributeMaxDynamicSharedMemorySize, FUSE_SMEM);
        attr_done = true;
    }

    prepare_kernel<<<NB_TOTAL, 256>>>(xs, xd, emb, lin, W0, W1, W2);
    gemm_mma0<<<dim3(128, 4), 256, GEMM0_SMEM>>>(b0);
    gemm12_head<<<128, 256, FUSE_SMEM>>>(b1, b2, Wout, bout, out);
}

// round 15
// speedup vs baseline: 1.0159x; 1.0159x over previous
#include <cuda_runtime.h>
#include <cuda_fp16.h>
#include <cstdint>

// ---------------------------------------------------------------------------
// DeepFM on GB300 (compute_103 -> HMMA mma.sync path):  [R13 configuration]
//   prepare (gather[unroll4] + 3x weight transpose merged, 1 launch)
//   -> gemm0 (CTA 128x256 f16-acc, 2 CTAs/SM, BK=32, NST=3, B via cp.async.ca,
//             grid (128,4) M-fast so co-resident CTAs share the B tile)
//   -> gemm12_head (M=128, phase1 NST=4 warp 64x128 f16-acc -> h2 in smem,
//                   phase2 warp 64x64 f16-acc, fused 256->1 head + sigmoid)
// ---------------------------------------------------------------------------

#define B_ROWS 16384
#define NFIELD 26
#define VOCAB  100000
#define EDIM   32
#define NDENSE 13
#define K0PAD  864

__device__ __half g_h0[(size_t)B_ROWS * K0PAD];
__device__ __half g_h1[(size_t)B_ROWS * 1024];
__device__ float  g_logit0[B_ROWS];
__device__ __half g_W0t[(size_t)1024 * K0PAD];  // [N,K] K-major fp16
__device__ __half g_W1t[(size_t)512 * 1024];
__device__ __half g_W2t[(size_t)256 * 512];

// ---------------------------------------------------------------------------
__device__ __forceinline__ uint32_t smem_to_u32(const void* p) {
    uint32_t a;
    asm("{ .reg .u64 t; cvta.to.shared.u64 t, %1; cvt.u32.u64 %0, t; }"
        : "=r"(a) : "l"(p));
    return a;
}
__device__ __forceinline__ void cp_async16(uint32_t dst, const void* src) {
    asm volatile("cp.async.cg.shared.global [%0], [%1], 16;"
                 :: "r"(dst), "l"(src) : "memory");
}
__device__ __forceinline__ void cp_async16_ca(uint32_t dst, const void* src) {
    asm volatile("cp.async.ca.shared.global [%0], [%1], 16;"
                 :: "r"(dst), "l"(src) : "memory");
}
__device__ __forceinline__ void cp_commit() {
    asm volatile("cp.async.commit_group;" ::: "memory");
}
template <int N>
__device__ __forceinline__ void cp_wait() {
    asm volatile("cp.async.wait_group %0;" :: "n"(N) : "memory");
}
__device__ __forceinline__ void ldsm_x4(uint32_t* r, uint32_t addr) {
    asm volatile("ldmatrix.sync.aligned.m8n8.x4.shared.b16 {%0,%1,%2,%3}, [%4];"
                 : "=r"(r[0]), "=r"(r[1]), "=r"(r[2]), "=r"(r[3]) : "r"(addr));
}
__device__ __forceinline__ void mma_f16(uint32_t* c, const uint32_t* a,
                                        uint32_t b0, uint32_t b1) {
    asm volatile(
        "mma.sync.aligned.m16n8k16.row.col.f16.f16.f16.f16 "
        "{%0,%1}, {%2,%3,%4,%5}, {%6,%7}, {%0,%1};"
        : "+r"(c[0]), "+r"(c[1])
        : "r"(a[0]), "r"(a[1]), "r"(a[2]), "r"(a[3]), "r"(b0), "r"(b1));
}

// ---------------------------------------------------------------------------
// Merged prepare kernel: block-range dispatch.
#define NB_P0 (27 * 32)
#define NB_P1 (32 * 16)
#define NB_P2 (16 * 8)
#define NB_PREP (NB_P0 + NB_P1 + NB_P2)       // 1504
#define NB_GATHER (B_ROWS / 8)                // 2048
#define NB_TOTAL (NB_PREP + NB_GATHER)        // 3552

__device__ __forceinline__ void transpose_tile(
    const float* __restrict__ W, __half* __restrict__ out,
    int N, int K, int KP, int bk, int bn, float (*sm)[33])
{
    const int tx = threadIdx.x & 31, ty = threadIdx.x >> 5;
    #pragma unroll
    for (int i = 0; i < 4; ++i) {
        int k = bk + ty + 8 * i;
        sm[ty + 8 * i][tx] = (k < K) ? __ldg(W + (size_t)k * N + bn + tx) : 0.0f;
    }
    __syncthreads();
    #pragma unroll
    for (int i = 0; i < 4; ++i) {
        int n = bn + ty + 8 * i;
        out[(size_t)n * KP + bk + tx] = __float2half(sm[tx][ty + 8 * i]);
    }
}

__global__ __launch_bounds__(256)
void prepare_kernel(const int* __restrict__ xs,
                    const float* __restrict__ xd,
                    const float* __restrict__ emb,
                    const float* __restrict__ lin,
                    const float* __restrict__ W0,
                    const float* __restrict__ W1,
                    const float* __restrict__ W2) {
    __shared__ float sm[32][33];
    const int blk = blockIdx.x;

    if (blk < NB_P0) {
        transpose_tile(W0, g_W0t, 1024, 845, K0PAD,
                       (blk % 27) * 32, (blk / 27) * 32, sm);
        return;
    }
    if (blk < NB_P0 + NB_P1) {
        const int b = blk - NB_P0;
        transpose_tile(W1, g_W1t, 512, 1024, 1024,
                       (b % 32) * 32, (b / 32) * 32, sm);
        return;
    }
    if (blk < NB_PREP) {
        const int b = blk - NB_P0 - NB_P1;
        transpose_tile(W2, g_W2t, 256, 512, 512,
                       (b % 16) * 32, (b / 16) * 32, sm);
        return;
    }

    // ---- gather: 8 warps per block, one batch row per warp, unroll 4 ----
    const int wid  = threadIdx.x >> 5;
    const int lane = threadIdx.x & 31;
    const int b    = (blk - NB_PREP) * 8 + wid;

    int   idx_l = 0;
    float linv  = 0.0f;
    if (lane < NFIELD) {
        idx_l = xs[b * NFIELD + lane];
        linv  = __ldg(lin + (size_t)lane * VOCAB + idx_l);
    }

    float s = 0.0f, ss = 0.0f;
    __half* h0row = g_h0 + (size_t)b * K0PAD;

    #pragma unroll
    for (int f0 = 0; f0 < 24; f0 += 4) {
        float v[4];
        #pragma unroll
        for (int u = 0; u < 4; ++u) {
            int idx = __shfl_sync(0xffffffffu, idx_l, f0 + u);
            v[u] = __ldg(emb + ((size_t)(f0 + u) * VOCAB + idx) * EDIM + lane);
        }
        #pragma unroll
        for (int u = 0; u < 4; ++u) {
            s  += v[u];
            ss += v[u] * v[u];
            h0row[(f0 + u) * EDIM + lane] = __float2half(v[u]);
        }
    }
    {
        float v[2];
        #pragma unroll
        for (int u = 0; u < 2; ++u) {
            int idx = __shfl_sync(0xffffffffu, idx_l, 24 + u);
            v[u] = __ldg(emb + ((size_t)(24 + u) * VOCAB + idx) * EDIM + lane);
        }
        #pragma unroll
        for (int u = 0; u < 2; ++u) {
            s  += v[u];
            ss += v[u] * v[u];
            h0row[(24 + u) * EDIM + lane] = __float2half(v[u]);
        }
    }
    h0row[NFIELD * EDIM + lane] =
        __float2half((lane < NDENSE) ? xd[b * NDENSE + lane] : 0.0f);

    float s2 = s * s;
    #pragma unroll
    for (int o = 16; o; o >>= 1) {
        ss   += __shfl_xor_sync(0xffffffffu, ss,   o);
        s2   += __shfl_xor_sync(0xffffffffu, s2,   o);
        linv += __shfl_xor_sync(0xffffffffu, linv, o);
    }
    if (lane == 0) g_logit0[b] = linv + 0.5f * (s2 - ss);
}

// ---------------------------------------------------------------------------
#define BK       32
#define AROWB    80                        // bytes/row: 64 + 16 pad

// ===== gemm0: CTA 128x256, 8 warps (2M x 4N), warp 64x64, f16 acc,
//       2 CTAs/SM, NST=3, grid (128, 4): x = bm (fast), y = bn -> co-resident
//       CTAs share the same B tile; A via .cg, B via .ca.
#define AT0      (128 * AROWB)             // 10240
#define BT0      (256 * AROWB)             // 20480
#define ST0      (AT0 + BT0)               // 30720
#define NST0     3
#define GEMM0_SMEM (NST0 * ST0)            // 92160

__global__ __launch_bounds__(256, 2)
void gemm_mma0(const float* __restrict__ bias) {
    extern __shared__ char smem[];
    const uint32_t sbase = smem_to_u32(smem);
    const int tid = threadIdx.x;
    const int warp = tid >> 5, lane = tid & 31;
    const int wm = (warp & 1) * 64, wn = (warp >> 1) * 64;
    const int bm = blockIdx.x * 128, bn = blockIdx.y * 256;   // x = M (fast)
    const int KIT = K0PAD / BK;            // 27

    const __half* A  = g_h0;
    const __half* Bw = g_W0t + (size_t)bn * K0PAD;

    const int row0 = tid >> 2, seg = tid & 3;

    auto issue = [&](int it) {
        if (it < KIT) {
            const int k0 = it * BK;
            const uint32_t st = sbase + (it % NST0) * ST0;
            cp_async16(st + row0 * AROWB + seg * 16,
                       A + (size_t)(bm + row0) * K0PAD + k0 + seg * 8);
            cp_async16(st + (row0 + 64) * AROWB + seg * 16,
                       A + (size_t)(bm + row0 + 64) * K0PAD + k0 + seg * 8);
            const uint32_t sb = st + AT0;
            #pragma unroll
            for (int j = 0; j < 4; ++j)
                cp_async16_ca(sb + (row0 + 64 * j) * AROWB + seg * 16,
                              Bw + (size_t)(row0 + 64 * j) * K0PAD + k0 + seg * 8);
        }
        cp_commit();
    };

    #pragma unroll
    for (int s = 0; s < NST0 - 1; ++s) issue(s);

    uint32_t c[4][8][2];
    #pragma unroll
    for (int i = 0; i < 4; ++i)
        #pragma unroll
        for (int j = 0; j < 8; ++j) { c[i][j][0] = 0u; c[i][j][1] = 0u; }

    const int a_row  = wm + (lane & 15);
    const int a_koff = (lane >> 4) * 8;
    const int b_row  = wn + (lane & 7) + ((lane >> 4) << 3);
    const int b_koff = (lane & 8);

    for (int i = 0; i < KIT; ++i) {
        cp_wait<NST0 - 2>();
        __syncthreads();
        issue(i + NST0 - 1);

        const uint32_t sa = sbase + (i % NST0) * ST0;
        const uint32_t sb = sa + AT0;

        #pragma unroll
        for (int kk = 0; kk < 2; ++kk) {
            uint32_t a[4][4], b[4][4];
            #pragma unroll
            for (int mt = 0; mt < 4; ++mt)
                ldsm_x4(a[mt], sa + (a_row + mt * 16) * AROWB + (kk * 16 + a_koff) * 2);
            #pragma unroll
            for (int nt = 0; nt < 4; ++nt)
                ldsm_x4(b[nt], sb + (b_row + nt * 16) * AROWB + (kk * 16 + b_koff) * 2);
            #pragma unroll
            for (int mt = 0; mt < 4; ++mt)
                #pragma unroll
                for (int nt = 0; nt < 4; ++nt) {
                    mma_f16(c[mt][2 * nt],     a[mt], b[nt][0], b[nt][1]);
                    mma_f16(c[mt][2 * nt + 1], a[mt], b[nt][2], b[nt][3]);
                }
        }
    }

    const __half2 z2 = __float2half2_rn(0.0f);
    #pragma unroll
    for (int mt = 0; mt < 4; ++mt) {
        const size_t r0 = (size_t)bm + wm + mt * 16 + (lane >> 2);
        #pragma unroll
        for (int j = 0; j < 8; ++j) {
            const int col = bn + wn + j * 8 + 2 * (lane & 3);
            const float2 bf = *reinterpret_cast<const float2*>(bias + col);
            const __half2 bb = __floats2half2_rn(bf.x, bf.y);
            __half2 lo = *reinterpret_cast<__half2*>(&c[mt][j][0]);
            __half2 hi = *reinterpret_cast<__half2*>(&c[mt][j][1]);
            lo = __hmax2(__hadd2(lo, bb), z2);
            hi = __hmax2(__hadd2(hi, bb), z2);
            *reinterpret_cast<__half2*>(g_h1 + r0 * 1024 + col)       = lo;
            *reinterpret_cast<__half2*>(g_h1 + (r0 + 8) * 1024 + col) = hi;
        }
    }
}

// ---------------------------------------------------------------------------
// Fused layers 1+2+head. Grid = 128 CTAs x 256 threads.
#define AT1      (128 * AROWB)             // 10240
#define BT1      (512 * AROWB)             // 40960
#define ST1      (AT1 + BT1)               // 51200
#define NST1     4
#define PIPE1    (NST1 * ST1)              // 204800

#define H2PITCH  520                       // halves (512 + 8 pad)
#define H2BYTES  (128 * H2PITCH * 2)       // 133120
#define P2OFF    H2BYTES
#define BT2      (256 * AROWB)             // 20480
#define NST2     3
#define FUSE_SMEM 204800
#define H3PITCH  264

__global__ __launch_bounds__(256, 1)
void gemm12_head(const float* __restrict__ b1,
                 const float* __restrict__ b2,
                 const float* __restrict__ Wout,
                 const float* __restrict__ bout,
                 float* __restrict__ out) {
    extern __shared__ char smem[];
    const uint32_t sbase = smem_to_u32(smem);
    __half* s_h2 = reinterpret_cast<__half*>(smem);
    __half* s_h3 = reinterpret_cast<__half*>(smem);

    const int tid = threadIdx.x;
    const int warp = tid >> 5, lane = tid & 31;
    const int bm = blockIdx.x * 128;
    const __half2 z2 = __float2half2_rn(0.0f);

    // ---- Phase 1: layer 1 (K=1024, N=512), warp 64x128, f16 acc ----
    {
        const int wm = (warp & 1) * 64, wn = (warp >> 1) * 128;
        const int KIT = 1024 / BK;   // 32
        const int row0 = tid >> 2, seg = tid & 3;

        auto issue = [&](int it) {
            if (it < KIT) {
                const int k0 = it * BK;
                const uint32_t st = sbase + (it % NST1) * ST1;
                cp_async16(st + row0 * AROWB + seg * 16,
                           g_h1 + (size_t)(bm + row0) * 1024 + k0 + seg * 8);
                cp_async16(st + (row0 + 64) * AROWB + seg * 16,
                           g_h1 + (size_t)(bm + row0 + 64) * 1024 + k0 + seg * 8);
                const uint32_t sb = st + AT1;
                #pragma unroll
                for (int j = 0; j < 8; ++j)
                    cp_async16(sb + (row0 + 64 * j) * AROWB + seg * 16,
                               g_W1t + (size_t)(row0 + 64 * j) * 1024 + k0 + seg * 8);
            }
            cp_commit();
        };

        #pragma unroll
        for (int s = 0; s < NST1 - 1; ++s) issue(s);

        uint32_t c[4][16][2];
        #pragma unroll
        for (int i = 0; i < 4; ++i)
            #pragma unroll
            for (int j = 0; j < 16; ++j) { c[i][j][0] = 0u; c[i][j][1] = 0u; }

        const int a_row  = wm + (lane & 15);
        const int a_koff = (lane >> 4) * 8;
        const int b_row  = wn + (lane & 7) + ((lane >> 4) << 3);
        const int b_koff = (lane & 8);

        for (int i = 0; i < KIT; ++i) {
            cp_wait<NST1 - 2>();
            __syncthreads();
            issue(i + NST1 - 1);

            const uint32_t sa = sbase + (i % NST1) * ST1;
            const uint32_t sb = sa + AT1;

            #pragma unroll
            for (int kk = 0; kk < 2; ++kk) {
                uint32_t a[4][4], b[8][4];
                #pragma unroll
                for (int mt = 0; mt < 4; ++mt)
                    ldsm_x4(a[mt], sa + (a_row + mt * 16) * AROWB + (kk * 16 + a_koff) * 2);
                #pragma unroll
                for (int nt = 0; nt < 8; ++nt)
                    ldsm_x4(b[nt], sb + (b_row + nt * 16) * AROWB + (kk * 16 + b_koff) * 2);
                #pragma unroll
                for (int mt = 0; mt < 4; ++mt)
                    #pragma unroll
                    for (int nt = 0; nt < 8; ++nt) {
                        mma_f16(c[mt][2 * nt],     a[mt], b[nt][0], b[nt][1]);
                        mma_f16(c[mt][2 * nt + 1], a[mt], b[nt][2], b[nt][3]);
                    }
            }
        }
        __syncthreads();   // pipeline dead; safe to overwrite with h2

        #pragma unroll
        for (int mt = 0; mt < 4; ++mt) {
            const int r0 = wm + mt * 16 + (lane >> 2);
            #pragma unroll
            for (int nt = 0; nt < 16; ++nt) {
                const int col = wn + nt * 8 + 2 * (lane & 3);
                const float2 bf = *reinterpret_cast<const float2*>(b1 + col);
                const __half2 bb = __floats2half2_rn(bf.x, bf.y);
                __half2 lo = *reinterpret_cast<__half2*>(&c[mt][nt][0]);
                __half2 hi = *reinterpret_cast<__half2*>(&c[mt][nt][1]);
                lo = __hmax2(__hadd2(lo, bb), z2);
                hi = __hmax2(__hadd2(hi, bb), z2);
                *reinterpret_cast<__half2*>(s_h2 + r0 * H2PITCH + col)       = lo;
                *reinterpret_cast<__half2*>(s_h2 + (r0 + 8) * H2PITCH + col) = hi;
            }
        }
    }
    __syncthreads();

    // ---- Phase 2: layer 2 (K=512, N=256), warp 64x64, f16 acc ----
    uint32_t c2[4][8][2];
    {
        const int wm = (warp & 1) * 64, wn = (warp >> 1) * 64;
        const int KIT = 512 / BK;   // 16
        const int row0 = tid >> 2, seg = tid & 3;

        auto issueB = [&](int it) {
            if (it < KIT) {
                const int k0 = it * BK;
                const uint32_t st = sbase + P2OFF + (it % NST2) * BT2;
                #pragma unroll
                for (int j = 0; j < 4; ++j)
                    cp_async16(st + (row0 + 64 * j) * AROWB + seg * 16,
                               g_W2t + (size_t)(row0 + 64 * j) * 512 + k0 + seg * 8);
            }
            cp_commit();
        };
        #pragma unroll
        for (int s = 0; s < NST2 - 1; ++s) issueB(s);

        #pragma unroll
        for (int i = 0; i < 4; ++i)
            #pragma unroll
            for (int j = 0; j < 8; ++j) { c2[i][j][0] = 0u; c2[i][j][1] = 0u; }

        const int a_row  = wm + (lane & 15);
        const int a_koff = (lane >> 4) * 8;
        const int b_row  = wn + (lane & 7) + ((lane >> 4) << 3);
        const int b_koff = (lane & 8);

        for (int i = 0; i < KIT; ++i) {
            cp_wait<NST2 - 2>();
            __syncthreads();
            issueB(i + NST2 - 1);

            const uint32_t sb = sbase + P2OFF + (i % NST2) * BT2;

            #pragma unroll
            for (int kk = 0; kk < 2; ++kk) {
                uint32_t a[4][4], b[4][4];
                #pragma unroll
                for (int mt = 0; mt < 4; ++mt)
                    ldsm_x4(a[mt], sbase + (a_row + mt * 16) * (H2PITCH * 2)
                                       + (i * 32 + kk * 16 + a_koff) * 2);
                #pragma unroll
                for (int nt = 0; nt < 4; ++nt)
                    ldsm_x4(b[nt], sb + (b_row + nt * 16) * AROWB + (kk * 16 + b_koff) * 2);
                #pragma unroll
                for (int mt = 0; mt < 4; ++mt)
                    #pragma unroll
                    for (int nt = 0; nt < 4; ++nt) {
                        mma_f16(c2[mt][2 * nt],     a[mt], b[nt][0], b[nt][1]);
                        mma_f16(c2[mt][2 * nt + 1], a[mt], b[nt][2], b[nt][3]);
                    }
            }
        }
    }
    __syncthreads();   // h2 dead; reuse offset 0 for h3

    // ---- Phase 3: h3 -> smem, head ----
    {
        const int wm = (warp & 1) * 64, wn = (warp >> 1) * 64;
        #pragma unroll
        for (int mt = 0; mt < 4; ++mt) {
            const int r0 = wm + mt * 16 + (lane >> 2);
            #pragma unroll
            for (int j = 0; j < 8; ++j) {
                const int col = wn + j * 8 + 2 * (lane & 3);
                const float2 bf = *reinterpret_cast<const float2*>(b2 + col);
                const __half2 bb = __floats2half2_rn(bf.x, bf.y);
                __half2 lo = *reinterpret_cast<__half2*>(&c2[mt][j][0]);
                __half2 hi = *reinterpret_cast<__half2*>(&c2[mt][j][1]);
                lo = __hmax2(__hadd2(lo, bb), z2);
                hi = __hmax2(__hadd2(hi, bb), z2);
                *reinterpret_cast<__half2*>(s_h3 + r0 * H3PITCH + col)       = lo;
                *reinterpret_cast<__half2*>(s_h3 + (r0 + 8) * H3PITCH + col) = hi;
            }
        }
    }
    __syncthreads();

    float wreg[8];
    #pragma unroll
    for (int j = 0; j < 8; ++j) wreg[j] = __ldg(Wout + j * 32 + lane);
    const float bo = __ldg(bout);

    #pragma unroll 1
    for (int t = 0; t < 16; ++t) {
        const int row = warp * 16 + t;
        float acc = 0.0f;
        #pragma unroll
        for (int j = 0; j < 8; ++j)
            acc += __half2float(s_h3[row * H3PITCH + j * 32 + lane]) * wreg[j];
        #pragma unroll
        for (int o = 16; o; o >>= 1) acc += __shfl_xor_sync(0xffffffffu, acc, o);
        if (lane == 0) {
            float logit = acc + bo + g_logit0[bm + row];
            out[bm + row] = 1.0f / (1.0f + expf(-logit));
        }
    }
}

// ---------------------------------------------------------------------------
extern "C" void kernel_launch(void* const* d_in, const int* in_sizes, int n_in,
                              void* d_out, int out_size) {
    const int*   xs   = (const int*)  d_in[0];
    const float* xd   = (const float*)d_in[1];
    const float* emb  = (const float*)d_in[2];
    const float* lin  = (const float*)d_in[3];
    const float* W0   = (const float*)d_in[4];
    const float* b0   = (const float*)d_in[5];
    const float* W1   = (const float*)d_in[6];
    const float* b1   = (const float*)d_in[7];
    const float* W2   = (const float*)d_in[8];
    const float* b2   = (const float*)d_in[9];
    const float* Wout = (const float*)d_in[10];
    const float* bout = (const float*)d_in[11];
    float* out = (float*)d_out;

    static bool attr_done = false;
    if (!attr_done) {
        cudaFuncSetAttribute(gemm_mma0,
                             cudaFuncAttributeMaxDynamicSharedMemorySize, GEMM0_SMEM);
        cudaFuncSetAttribute(gemm12_head,
                             cudaFuncAttributeMaxDynamicSharedMemorySize, FUSE_SMEM);
        attr_done = true;
    }

    prepare_kernel<<<NB_TOTAL, 256>>>(xs, xd, emb, lin, W0, W1, W2);
    gemm_mma0<<<dim3(128, 4), 256, GEMM0_SMEM>>>(b0);
    gemm12_head<<<128, 256, FUSE_SMEM>>>(b1, b2, Wout, bout, out);
}

// round 16
// speedup vs baseline: 1.0246x; 1.0085x over previous
#include <cuda_runtime.h>
#include <cuda_fp16.h>
#include <cstdint>

// ---------------------------------------------------------------------------
// DeepFM on GB300 (compute_103 -> HMMA mma.sync path):  [R13 + LPT prepare]
//   prepare (gather blocks FIRST, then 3x weight transpose; 1 launch)
//   -> gemm0 (CTA 128x256 f16-acc, 2 CTAs/SM, BK=32, NST=3, B via cp.async.ca,
//             grid (128,4) M-fast so co-resident CTAs share the B tile)
//   -> gemm12_head (M=128, phase1 NST=4 warp 64x128 f16-acc -> h2 in smem,
//                   phase2 warp 64x64 f16-acc, fused 256->1 head + sigmoid)
// ---------------------------------------------------------------------------

#define B_ROWS 16384
#define NFIELD 26
#define VOCAB  100000
#define EDIM   32
#define NDENSE 13
#define K0PAD  864

__device__ __half g_h0[(size_t)B_ROWS * K0PAD];
__device__ __half g_h1[(size_t)B_ROWS * 1024];
__device__ float  g_logit0[B_ROWS];
__device__ __half g_W0t[(size_t)1024 * K0PAD];  // [N,K] K-major fp16
__device__ __half g_W1t[(size_t)512 * 1024];
__device__ __half g_W2t[(size_t)256 * 512];

// ---------------------------------------------------------------------------
__device__ __forceinline__ uint32_t smem_to_u32(const void* p) {
    uint32_t a;
    asm("{ .reg .u64 t; cvta.to.shared.u64 t, %1; cvt.u32.u64 %0, t; }"
        : "=r"(a) : "l"(p));
    return a;
}
__device__ __forceinline__ void cp_async16(uint32_t dst, const void* src) {
    asm volatile("cp.async.cg.shared.global [%0], [%1], 16;"
                 :: "r"(dst), "l"(src) : "memory");
}
__device__ __forceinline__ void cp_async16_ca(uint32_t dst, const void* src) {
    asm volatile("cp.async.ca.shared.global [%0], [%1], 16;"
                 :: "r"(dst), "l"(src) : "memory");
}
__device__ __forceinline__ void cp_commit() {
    asm volatile("cp.async.commit_group;" ::: "memory");
}
template <int N>
__device__ __forceinline__ void cp_wait() {
    asm volatile("cp.async.wait_group %0;" :: "n"(N) : "memory");
}
__device__ __forceinline__ void ldsm_x4(uint32_t* r, uint32_t addr) {
    asm volatile("ldmatrix.sync.aligned.m8n8.x4.shared.b16 {%0,%1,%2,%3}, [%4];"
                 : "=r"(r[0]), "=r"(r[1]), "=r"(r[2]), "=r"(r[3]) : "r"(addr));
}
__device__ __forceinline__ void mma_f16(uint32_t* c, const uint32_t* a,
                                        uint32_t b0, uint32_t b1) {
    asm volatile(
        "mma.sync.aligned.m16n8k16.row.col.f16.f16.f16.f16 "
        "{%0,%1}, {%2,%3,%4,%5}, {%6,%7}, {%0,%1};"
        : "+r"(c[0]), "+r"(c[1])
        : "r"(a[0]), "r"(a[1]), "r"(a[2]), "r"(a[3]), "r"(b0), "r"(b1));
}

// ---------------------------------------------------------------------------
// Merged prepare kernel: LPT block ordering — long gather blocks first,
// short transpose blocks backfill the tail.
#define NB_GATHER (B_ROWS / 8)                // 2048
#define NB_P0 (27 * 32)                       // 864
#define NB_P1 (32 * 16)                       // 512
#define NB_P2 (16 * 8)                        // 128
#define NB_TOTAL (NB_GATHER + NB_P0 + NB_P1 + NB_P2)  // 3552

__device__ __forceinline__ void transpose_tile(
    const float* __restrict__ W, __half* __restrict__ out,
    int N, int K, int KP, int bk, int bn, float (*sm)[33])
{
    const int tx = threadIdx.x & 31, ty = threadIdx.x >> 5;
    #pragma unroll
    for (int i = 0; i < 4; ++i) {
        int k = bk + ty + 8 * i;
        sm[ty + 8 * i][tx] = (k < K) ? __ldg(W + (size_t)k * N + bn + tx) : 0.0f;
    }
    __syncthreads();
    #pragma unroll
    for (int i = 0; i < 4; ++i) {
        int n = bn + ty + 8 * i;
        out[(size_t)n * KP + bk + tx] = __float2half(sm[tx][ty + 8 * i]);
    }
}

__global__ __launch_bounds__(256)
void prepare_kernel(const int* __restrict__ xs,
                    const float* __restrict__ xd,
                    const float* __restrict__ emb,
                    const float* __restrict__ lin,
                    const float* __restrict__ W0,
                    const float* __restrict__ W1,
                    const float* __restrict__ W2) {
    __shared__ float sm[32][33];
    const int blk = blockIdx.x;

    if (blk >= NB_GATHER) {
        // ---- weight transposes (short blocks, scheduled last) ----
        const int tb = blk - NB_GATHER;
        if (tb < NB_P0) {
            transpose_tile(W0, g_W0t, 1024, 845, K0PAD,
                           (tb % 27) * 32, (tb / 27) * 32, sm);
        } else if (tb < NB_P0 + NB_P1) {
            const int b = tb - NB_P0;
            transpose_tile(W1, g_W1t, 512, 1024, 1024,
                           (b % 32) * 32, (b / 32) * 32, sm);
        } else {
            const int b = tb - NB_P0 - NB_P1;
            transpose_tile(W2, g_W2t, 256, 512, 512,
                           (b % 16) * 32, (b / 16) * 32, sm);
        }
        return;
    }

    // ---- gather: 8 warps per block, one batch row per warp, unroll 4 ----
    const int wid  = threadIdx.x >> 5;
    const int lane = threadIdx.x & 31;
    const int b    = blk * 8 + wid;

    int   idx_l = 0;
    float linv  = 0.0f;
    if (lane < NFIELD) {
        idx_l = xs[b * NFIELD + lane];
        linv  = __ldg(lin + (size_t)lane * VOCAB + idx_l);
    }

    float s = 0.0f, ss = 0.0f;
    __half* h0row = g_h0 + (size_t)b * K0PAD;

    #pragma unroll
    for (int f0 = 0; f0 < 24; f0 += 4) {
        float v[4];
        #pragma unroll
        for (int u = 0; u < 4; ++u) {
            int idx = __shfl_sync(0xffffffffu, idx_l, f0 + u);
            v[u] = __ldg(emb + ((size_t)(f0 + u) * VOCAB + idx) * EDIM + lane);
        }
        #pragma unroll
        for (int u = 0; u < 4; ++u) {
            s  += v[u];
            ss += v[u] * v[u];
            h0row[(f0 + u) * EDIM + lane] = __float2half(v[u]);
        }
    }
    {
        float v[2];
        #pragma unroll
        for (int u = 0; u < 2; ++u) {
            int idx = __shfl_sync(0xffffffffu, idx_l, 24 + u);
            v[u] = __ldg(emb + ((size_t)(24 + u) * VOCAB + idx) * EDIM + lane);
        }
        #pragma unroll
        for (int u = 0; u < 2; ++u) {
            s  += v[u];
            ss += v[u] * v[u];
            h0row[(24 + u) * EDIM + lane] = __float2half(v[u]);
        }
    }
    h0row[NFIELD * EDIM + lane] =
        __float2half((lane < NDENSE) ? xd[b * NDENSE + lane] : 0.0f);

    float s2 = s * s;
    #pragma unroll
    for (int o = 16; o; o >>= 1) {
        ss   += __shfl_xor_sync(0xffffffffu, ss,   o);
        s2   += __shfl_xor_sync(0xffffffffu, s2,   o);
        linv += __shfl_xor_sync(0xffffffffu, linv, o);
    }
    if (lane == 0) g_logit0[b] = linv + 0.5f * (s2 - ss);
}

// ---------------------------------------------------------------------------
#define BK       32
#define AROWB    80                        // bytes/row: 64 + 16 pad

// ===== gemm0: CTA 128x256, 8 warps (2M x 4N), warp 64x64, f16 acc,
//       2 CTAs/SM, NST=3, grid (128, 4): x = bm (fast), y = bn -> co-resident
//       CTAs share the same B tile; A via .cg, B via .ca.
#define AT0      (128 * AROWB)             // 10240
#define BT0      (256 * AROWB)             // 20480
#define ST0      (AT0 + BT0)               // 30720
#define NST0     3
#define GEMM0_SMEM (NST0 * ST0)            // 92160

__global__ __launch_bounds__(256, 2)
void gemm_mma0(const float* __restrict__ bias) {
    extern __shared__ char smem[];
    const uint32_t sbase = smem_to_u32(smem);
    const int tid = threadIdx.x;
    const int warp = tid >> 5, lane = tid & 31;
    const int wm = (warp & 1) * 64, wn = (warp >> 1) * 64;
    const int bm = blockIdx.x * 128, bn = blockIdx.y * 256;   // x = M (fast)
    const int KIT = K0PAD / BK;            // 27

    const __half* A  = g_h0;
    const __half* Bw = g_W0t + (size_t)bn * K0PAD;

    const int row0 = tid >> 2, seg = tid & 3;

    auto issue = [&](int it) {
        if (it < KIT) {
            const int k0 = it * BK;
            const uint32_t st = sbase + (it % NST0) * ST0;
            cp_async16(st + row0 * AROWB + seg * 16,
                       A + (size_t)(bm + row0) * K0PAD + k0 + seg * 8);
            cp_async16(st + (row0 + 64) * AROWB + seg * 16,
                       A + (size_t)(bm + row0 + 64) * K0PAD + k0 + seg * 8);
            const uint32_t sb = st + AT0;
            #pragma unroll
            for (int j = 0; j < 4; ++j)
                cp_async16_ca(sb + (row0 + 64 * j) * AROWB + seg * 16,
                              Bw + (size_t)(row0 + 64 * j) * K0PAD + k0 + seg * 8);
        }
        cp_commit();
    };

    #pragma unroll
    for (int s = 0; s < NST0 - 1; ++s) issue(s);

    uint32_t c[4][8][2];
    #pragma unroll
    for (int i = 0; i < 4; ++i)
        #pragma unroll
        for (int j = 0; j < 8; ++j) { c[i][j][0] = 0u; c[i][j][1] = 0u; }

    const int a_row  = wm + (lane & 15);
    const int a_koff = (lane >> 4) * 8;
    const int b_row  = wn + (lane & 7) + ((lane >> 4) << 3);
    const int b_koff = (lane & 8);

    for (int i = 0; i < KIT; ++i) {
        cp_wait<NST0 - 2>();
        __syncthreads();
        issue(i + NST0 - 1);

        const uint32_t sa = sbase + (i % NST0) * ST0;
        const uint32_t sb = sa + AT0;

        #pragma unroll
        for (int kk = 0; kk < 2; ++kk) {
            uint32_t a[4][4], b[4][4];
            #pragma unroll
            for (int mt = 0; mt < 4; ++mt)
                ldsm_x4(a[mt], sa + (a_row + mt * 16) * AROWB + (kk * 16 + a_koff) * 2);
            #pragma unroll
            for (int nt = 0; nt < 4; ++nt)
                ldsm_x4(b[nt], sb + (b_row + nt * 16) * AROWB + (kk * 16 + b_koff) * 2);
            #pragma unroll
            for (int mt = 0; mt < 4; ++mt)
                #pragma unroll
                for (int nt = 0; nt < 4; ++nt) {
                    mma_f16(c[mt][2 * nt],     a[mt], b[nt][0], b[nt][1]);
                    mma_f16(c[mt][2 * nt + 1], a[mt], b[nt][2], b[nt][3]);
                }
        }
    }

    const __half2 z2 = __float2half2_rn(0.0f);
    #pragma unroll
    for (int mt = 0; mt < 4; ++mt) {
        const size_t r0 = (size_t)bm + wm + mt * 16 + (lane >> 2);
        #pragma unroll
        for (int j = 0; j < 8; ++j) {
            const int col = bn + wn + j * 8 + 2 * (lane & 3);
            const float2 bf = *reinterpret_cast<const float2*>(bias + col);
            const __half2 bb = __floats2half2_rn(bf.x, bf.y);
            __half2 lo = *reinterpret_cast<__half2*>(&c[mt][j][0]);
            __half2 hi = *reinterpret_cast<__half2*>(&c[mt][j][1]);
            lo = __hmax2(__hadd2(lo, bb), z2);
            hi = __hmax2(__hadd2(hi, bb), z2);
            *reinterpret_cast<__half2*>(g_h1 + r0 * 1024 + col)       = lo;
            *reinterpret_cast<__half2*>(g_h1 + (r0 + 8) * 1024 + col) = hi;
        }
    }
}

// ---------------------------------------------------------------------------
// Fused layers 1+2+head. Grid = 128 CTAs x 256 threads.
#define AT1      (128 * AROWB)             // 10240
#define BT1      (512 * AROWB)             // 40960
#define ST1      (AT1 + BT1)               // 51200
#define NST1     4
#define PIPE1    (NST1 * ST1)              // 204800

#define H2PITCH  520                       // halves (512 + 8 pad)
#define H2BYTES  (128 * H2PITCH * 2)       // 133120
#define P2OFF    H2BYTES
#define BT2      (256 * AROWB)             // 20480
#define NST2     3
#define FUSE_SMEM 204800
#define H3PITCH  264

__global__ __launch_bounds__(256, 1)
void gemm12_head(const float* __restrict__ b1,
                 const float* __restrict__ b2,
                 const float* __restrict__ Wout,
                 const float* __restrict__ bout,
                 float* __restrict__ out) {
    extern __shared__ char smem[];
    const uint32_t sbase = smem_to_u32(smem);
    __half* s_h2 = reinterpret_cast<__half*>(smem);
    __half* s_h3 = reinterpret_cast<__half*>(smem);

    const int tid = threadIdx.x;
    const int warp = tid >> 5, lane = tid & 31;
    const int bm = blockIdx.x * 128;
    const __half2 z2 = __float2half2_rn(0.0f);

    // ---- Phase 1: layer 1 (K=1024, N=512), warp 64x128, f16 acc ----
    {
        const int wm = (warp & 1) * 64, wn = (warp >> 1) * 128;
        const int KIT = 1024 / BK;   // 32
        const int row0 = tid >> 2, seg = tid & 3;

        auto issue = [&](int it) {
            if (it < KIT) {
                const int k0 = it * BK;
                const uint32_t st = sbase + (it % NST1) * ST1;
                cp_async16(st + row0 * AROWB + seg * 16,
                           g_h1 + (size_t)(bm + row0) * 1024 + k0 + seg * 8);
                cp_async16(st + (row0 + 64) * AROWB + seg * 16,
                           g_h1 + (size_t)(bm + row0 + 64) * 1024 + k0 + seg * 8);
                const uint32_t sb = st + AT1;
                #pragma unroll
                for (int j = 0; j < 8; ++j)
                    cp_async16(sb + (row0 + 64 * j) * AROWB + seg * 16,
                               g_W1t + (size_t)(row0 + 64 * j) * 1024 + k0 + seg * 8);
            }
            cp_commit();
        };

        #pragma unroll
        for (int s = 0; s < NST1 - 1; ++s) issue(s);

        uint32_t c[4][16][2];
        #pragma unroll
        for (int i = 0; i < 4; ++i)
            #pragma unroll
            for (int j = 0; j < 16; ++j) { c[i][j][0] = 0u; c[i][j][1] = 0u; }

        const int a_row  = wm + (lane & 15);
        const int a_koff = (lane >> 4) * 8;
        const int b_row  = wn + (lane & 7) + ((lane >> 4) << 3);
        const int b_koff = (lane & 8);

        for (int i = 0; i < KIT; ++i) {
            cp_wait<NST1 - 2>();
            __syncthreads();
            issue(i + NST1 - 1);

            const uint32_t sa = sbase + (i % NST1) * ST1;
            const uint32_t sb = sa + AT1;

            #pragma unroll
            for (int kk = 0; kk < 2; ++kk) {
                uint32_t a[4][4], b[8][4];
                #pragma unroll
                for (int mt = 0; mt < 4; ++mt)
                    ldsm_x4(a[mt], sa + (a_row + mt * 16) * AROWB + (kk * 16 + a_koff) * 2);
                #pragma unroll
                for (int nt = 0; nt < 8; ++nt)
                    ldsm_x4(b[nt], sb + (b_row + nt * 16) * AROWB + (kk * 16 + b_koff) * 2);
                #pragma unroll
                for (int mt = 0; mt < 4; ++mt)
                    #pragma unroll
                    for (int nt = 0; nt < 8; ++nt) {
                        mma_f16(c[mt][2 * nt],     a[mt], b[nt][0], b[nt][1]);
                        mma_f16(c[mt][2 * nt + 1], a[mt], b[nt][2], b[nt][3]);
                    }
            }
        }
        __syncthreads();   // pipeline dead; safe to overwrite with h2

        #pragma unroll
        for (int mt = 0; mt < 4; ++mt) {
            const int r0 = wm + mt * 16 + (lane >> 2);
            #pragma unroll
            for (int nt = 0; nt < 16; ++nt) {
                const int col = wn + nt * 8 + 2 * (lane & 3);
                const float2 bf = *reinterpret_cast<const float2*>(b1 + col);
                const __half2 bb = __floats2half2_rn(bf.x, bf.y);
                __half2 lo = *reinterpret_cast<__half2*>(&c[mt][nt][0]);
                __half2 hi = *reinterpret_cast<__half2*>(&c[mt][nt][1]);
                lo = __hmax2(__hadd2(lo, bb), z2);
                hi = __hmax2(__hadd2(hi, bb), z2);
                *reinterpret_cast<__half2*>(s_h2 + r0 * H2PITCH + col)       = lo;
                *reinterpret_cast<__half2*>(s_h2 + (r0 + 8) * H2PITCH + col) = hi;
            }
        }
    }
    __syncthreads();

    // ---- Phase 2: layer 2 (K=512, N=256), warp 64x64, f16 acc ----
    uint32_t c2[4][8][2];
    {
        const int wm = (warp & 1) * 64, wn = (warp >> 1) * 64;
        const int KIT = 512 / BK;   // 16
        const int row0 = tid >> 2, seg = tid & 3;

        auto issueB = [&](int it) {
            if (it < KIT) {
                const int k0 = it * BK;
                const uint32_t st = sbase + P2OFF + (it % NST2) * BT2;
                #pragma unroll
                for (int j = 0; j < 4; ++j)
                    cp_async16(st + (row0 + 64 * j) * AROWB + seg * 16,
                               g_W2t + (size_t)(row0 + 64 * j) * 512 + k0 + seg * 8);
            }
            cp_commit();
        };
        #pragma unroll
        for (int s = 0; s < NST2 - 1; ++s) issueB(s);

        #pragma unroll
        for (int i = 0; i < 4; ++i)
            #pragma unroll
            for (int j = 0; j < 8; ++j) { c2[i][j][0] = 0u; c2[i][j][1] = 0u; }

        const int a_row  = wm + (lane & 15);
        const int a_koff = (lane >> 4) * 8;
        const int b_row  = wn + (lane & 7) + ((lane >> 4) << 3);
        const int b_koff = (lane & 8);

        for (int i = 0; i < KIT; ++i) {
            cp_wait<NST2 - 2>();
            __syncthreads();
            issueB(i + NST2 - 1);

            const uint32_t sb = sbase + P2OFF + (i % NST2) * BT2;

            #pragma unroll
            for (int kk = 0; kk < 2; ++kk) {
                uint32_t a[4][4], b[4][4];
                #pragma unroll
                for (int mt = 0; mt < 4; ++mt)
                    ldsm_x4(a[mt], sbase + (a_row + mt * 16) * (H2PITCH * 2)
                                       + (i * 32 + kk * 16 + a_koff) * 2);
                #pragma unroll
                for (int nt = 0; nt < 4; ++nt)
                    ldsm_x4(b[nt], sb + (b_row + nt * 16) * AROWB + (kk * 16 + b_koff) * 2);
                #pragma unroll
                for (int mt = 0; mt < 4; ++mt)
                    #pragma unroll
                    for (int nt = 0; nt < 4; ++nt) {
                        mma_f16(c2[mt][2 * nt],     a[mt], b[nt][0], b[nt][1]);
                        mma_f16(c2[mt][2 * nt + 1], a[mt], b[nt][2], b[nt][3]);
                    }
            }
        }
    }
    __syncthreads();   // h2 dead; reuse offset 0 for h3

    // ---- Phase 3: h3 -> smem, head ----
    {
        const int wm = (warp & 1) * 64, wn = (warp >> 1) * 64;
        #pragma unroll
        for (int mt = 0; mt < 4; ++mt) {
            const int r0 = wm + mt * 16 + (lane >> 2);
            #pragma unroll
            for (int j = 0; j < 8; ++j) {
                const int col = wn + j * 8 + 2 * (lane & 3);
                const float2 bf = *reinterpret_cast<const float2*>(b2 + col);
                const __half2 bb = __floats2half2_rn(bf.x, bf.y);
                __half2 lo = *reinterpret_cast<__half2*>(&c2[mt][j][0]);
                __half2 hi = *reinterpret_cast<__half2*>(&c2[mt][j][1]);
                lo = __hmax2(__hadd2(lo, bb), z2);
                hi = __hmax2(__hadd2(hi, bb), z2);
                *reinterpret_cast<__half2*>(s_h3 + r0 * H3PITCH + col)       = lo;
                *reinterpret_cast<__half2*>(s_h3 + (r0 + 8) * H3PITCH + col) = hi;
            }
        }
    }
    __syncthreads();

    float wreg[8];
    #pragma unroll
    for (int j = 0; j < 8; ++j) wreg[j] = __ldg(Wout + j * 32 + lane);
    const float bo = __ldg(bout);

    #pragma unroll 1
    for (int t = 0; t < 16; ++t) {
        const int row = warp * 16 + t;
        float acc = 0.0f;
        #pragma unroll
        for (int j = 0; j < 8; ++j)
            acc += __half2float(s_h3[row * H3PITCH + j * 32 + lane]) * wreg[j];
        #pragma unroll
        for (int o = 16; o; o >>= 1) acc += __shfl_xor_sync(0xffffffffu, acc, o);
        if (lane == 0) {
            float logit = acc + bo + g_logit0[bm + row];
            out[bm + row] = 1.0f / (1.0f + expf(-logit));
        }
    }
}

// ---------------------------------------------------------------------------
extern "C" void kernel_launch(void* const* d_in, const int* in_sizes, int n_in,
                              void* d_out, int out_size) {
    const int*   xs   = (const int*)  d_in[0];
    const float* xd   = (const float*)d_in[1];
    const float* emb  = (const float*)d_in[2];
    const float* lin  = (const float*)d_in[3];
    const float* W0   = (const float*)d_in[4];
    const float* b0   = (const float*)d_in[5];
    const float* W1   = (const float*)d_in[6];
    const float* b1   = (const float*)d_in[7];
    const float* W2   = (const float*)d_in[8];
    const float* b2   = (const float*)d_in[9];
    const float* Wout = (const float*)d_in[10];
    const float* bout = (const float*)d_in[11];
    float* out = (float*)d_out;

    static bool attr_done = false;
    if (!attr_done) {
        cudaFuncSetAttribute(gemm_mma0,
                             cudaFuncAttributeMaxDynamicSharedMemorySize, GEMM0_SMEM);
        cudaFuncSetAttribute(gemm12_head,
                             cudaFuncAttributeMaxDynamicSharedMemorySize, FUSE_SMEM);
        attr_done = true;
    }

    prepare_kernel<<<NB_TOTAL, 256>>>(xs, xd, emb, lin, W0, W1, W2);
    gemm_mma0<<<dim3(128, 4), 256, GEMM0_SMEM>>>(b0);
    gemm12_head<<<128, 256, FUSE_SMEM>>>(b1, b2, Wout, bout, out);
}

// round 17
// speedup vs baseline: 1.0260x; 1.0013x over previous
#include <cuda_runtime.h>
#include <cuda_fp16.h>
#include <cstdint>

// ---------------------------------------------------------------------------
// DeepFM on GB300 (compute_103 -> HMMA mma.sync path):
//   prepare (gather + W0 transpose; LPT: gather first)
//   -> gemm0 (CTA 128x256 f16-acc, 2 CTAs/SM, BK=32, NST=3, B via cp.async.ca,
//             M-fast 1D raster; W1/W2 transpose CTAs backfill the tail)
//   -> gemm12_head (M=128, phase1 NST=4 warp 64x128 f16-acc -> h2 in smem,
//                   phase2 warp 64x64 f16-acc, fused 256->1 head + sigmoid)
// ---------------------------------------------------------------------------

#define B_ROWS 16384
#define NFIELD 26
#define VOCAB  100000
#define EDIM   32
#define NDENSE 13
#define K0PAD  864

__device__ __half g_h0[(size_t)B_ROWS * K0PAD];
__device__ __half g_h1[(size_t)B_ROWS * 1024];
__device__ float  g_logit0[B_ROWS];
__device__ __half g_W0t[(size_t)1024 * K0PAD];  // [N,K] K-major fp16
__device__ __half g_W1t[(size_t)512 * 1024];
__device__ __half g_W2t[(size_t)256 * 512];

// ---------------------------------------------------------------------------
__device__ __forceinline__ uint32_t smem_to_u32(const void* p) {
    uint32_t a;
    asm("{ .reg .u64 t; cvta.to.shared.u64 t, %1; cvt.u32.u64 %0, t; }"
        : "=r"(a) : "l"(p));
    return a;
}
__device__ __forceinline__ void cp_async16(uint32_t dst, const void* src) {
    asm volatile("cp.async.cg.shared.global [%0], [%1], 16;"
                 :: "r"(dst), "l"(src) : "memory");
}
__device__ __forceinline__ void cp_async16_ca(uint32_t dst, const void* src) {
    asm volatile("cp.async.ca.shared.global [%0], [%1], 16;"
                 :: "r"(dst), "l"(src) : "memory");
}
__device__ __forceinline__ void cp_commit() {
    asm volatile("cp.async.commit_group;" ::: "memory");
}
template <int N>
__device__ __forceinline__ void cp_wait() {
    asm volatile("cp.async.wait_group %0;" :: "n"(N) : "memory");
}
__device__ __forceinline__ void ldsm_x4(uint32_t* r, uint32_t addr) {
    asm volatile("ldmatrix.sync.aligned.m8n8.x4.shared.b16 {%0,%1,%2,%3}, [%4];"
                 : "=r"(r[0]), "=r"(r[1]), "=r"(r[2]), "=r"(r[3]) : "r"(addr));
}
__device__ __forceinline__ void mma_f16(uint32_t* c, const uint32_t* a,
                                        uint32_t b0, uint32_t b1) {
    asm volatile(
        "mma.sync.aligned.m16n8k16.row.col.f16.f16.f16.f16 "
        "{%0,%1}, {%2,%3,%4,%5}, {%6,%7}, {%0,%1};"
        : "+r"(c[0]), "+r"(c[1])
        : "r"(a[0]), "r"(a[1]), "r"(a[2]), "r"(a[3]), "r"(b0), "r"(b1));
}

// ---------------------------------------------------------------------------
__device__ __forceinline__ void transpose_tile(
    const float* __restrict__ W, __half* __restrict__ out,
    int N, int K, int KP, int bk, int bn, float (*sm)[33])
{
    const int tx = threadIdx.x & 31, ty = threadIdx.x >> 5;
    #pragma unroll
    for (int i = 0; i < 4; ++i) {
        int k = bk + ty + 8 * i;
        sm[ty + 8 * i][tx] = (k < K) ? __ldg(W + (size_t)k * N + bn + tx) : 0.0f;
    }
    __syncthreads();
    #pragma unroll
    for (int i = 0; i < 4; ++i) {
        int n = bn + ty + 8 * i;
        out[(size_t)n * KP + bk + tx] = __float2half(sm[tx][ty + 8 * i]);
    }
}

// ---------------------------------------------------------------------------
// prepare: gather (long, first) + W0 transpose (short, tail).
#define NB_GATHER (B_ROWS / 8)                // 2048
#define NB_P0 (27 * 32)                       // 864
#define NB_PREP (NB_GATHER + NB_P0)           // 2912

__global__ __launch_bounds__(256)
void prepare_kernel(const int* __restrict__ xs,
                    const float* __restrict__ xd,
                    const float* __restrict__ emb,
                    const float* __restrict__ lin,
                    const float* __restrict__ W0) {
    __shared__ float sm[32][33];
    const int blk = blockIdx.x;

    if (blk >= NB_GATHER) {
        const int tb = blk - NB_GATHER;
        transpose_tile(W0, g_W0t, 1024, 845, K0PAD,
                       (tb % 27) * 32, (tb / 27) * 32, sm);
        return;
    }

    // ---- gather: 8 warps per block, one batch row per warp, unroll 4 ----
    const int wid  = threadIdx.x >> 5;
    const int lane = threadIdx.x & 31;
    const int b    = blk * 8 + wid;

    int   idx_l = 0;
    float linv  = 0.0f;
    if (lane < NFIELD) {
        idx_l = xs[b * NFIELD + lane];
        linv  = __ldg(lin + (size_t)lane * VOCAB + idx_l);
    }

    float s = 0.0f, ss = 0.0f;
    __half* h0row = g_h0 + (size_t)b * K0PAD;

    #pragma unroll
    for (int f0 = 0; f0 < 24; f0 += 4) {
        float v[4];
        #pragma unroll
        for (int u = 0; u < 4; ++u) {
            int idx = __shfl_sync(0xffffffffu, idx_l, f0 + u);
            v[u] = __ldg(emb + ((size_t)(f0 + u) * VOCAB + idx) * EDIM + lane);
        }
        #pragma unroll
        for (int u = 0; u < 4; ++u) {
            s  += v[u];
            ss += v[u] * v[u];
            h0row[(f0 + u) * EDIM + lane] = __float2half(v[u]);
        }
    }
    {
        float v[2];
        #pragma unroll
        for (int u = 0; u < 2; ++u) {
            int idx = __shfl_sync(0xffffffffu, idx_l, 24 + u);
            v[u] = __ldg(emb + ((size_t)(24 + u) * VOCAB + idx) * EDIM + lane);
        }
        #pragma unroll
        for (int u = 0; u < 2; ++u) {
            s  += v[u];
            ss += v[u] * v[u];
            h0row[(24 + u) * EDIM + lane] = __float2half(v[u]);
        }
    }
    h0row[NFIELD * EDIM + lane] =
        __float2half((lane < NDENSE) ? xd[b * NDENSE + lane] : 0.0f);

    float s2 = s * s;
    #pragma unroll
    for (int o = 16; o; o >>= 1) {
        ss   += __shfl_xor_sync(0xffffffffu, ss,   o);
        s2   += __shfl_xor_sync(0xffffffffu, s2,   o);
        linv += __shfl_xor_sync(0xffffffffu, linv, o);
    }
    if (lane == 0) g_logit0[b] = linv + 0.5f * (s2 - ss);
}

// ---------------------------------------------------------------------------
#define BK       32
#define AROWB    80                        // bytes/row: 64 + 16 pad

// ===== gemm0 + backfilled W1/W2 transposes. 1D grid:
//   [0, 512)      : GEMM CTAs, bm = (blk & 127)*128 (fast), bn = (blk >> 7)*256
//   [512, 1024)   : W1 transpose tiles (512)
//   [1024, 1152)  : W2 transpose tiles (128)
#define NB_G0     512
#define NB_W1     (32 * 16)                // 512
#define NB_W2     (16 * 8)                 // 128
#define NB_GEMM0  (NB_G0 + NB_W1 + NB_W2)  // 1152

#define AT0      (128 * AROWB)             // 10240
#define BT0      (256 * AROWB)             // 20480
#define ST0      (AT0 + BT0)               // 30720
#define NST0     3
#define GEMM0_SMEM (NST0 * ST0)            // 92160 dynamic (+4224 static)

__global__ __launch_bounds__(256, 2)
void gemm_mma0(const float* __restrict__ bias,
               const float* __restrict__ W1,
               const float* __restrict__ W2) {
    __shared__ float sm_t[32][33];         // for transpose CTAs (4224 B)
    const int blk = blockIdx.x;

    if (blk >= NB_G0) {
        const int tb = blk - NB_G0;
        if (tb < NB_W1) {
            transpose_tile(W1, g_W1t, 512, 1024, 1024,
                           (tb % 32) * 32, (tb / 32) * 32, sm_t);
        } else {
            const int b = tb - NB_W1;
            transpose_tile(W2, g_W2t, 256, 512, 512,
                           (b % 16) * 32, (b / 16) * 32, sm_t);
        }
        return;
    }

    extern __shared__ char smem[];
    const uint32_t sbase = smem_to_u32(smem);
    const int tid = threadIdx.x;
    const int warp = tid >> 5, lane = tid & 31;
    const int wm = (warp & 1) * 64, wn = (warp >> 1) * 64;
    const int bm = (blk & 127) * 128, bn = (blk >> 7) * 256;  // M fastest
    const int KIT = K0PAD / BK;            // 27

    const __half* A  = g_h0;
    const __half* Bw = g_W0t + (size_t)bn * K0PAD;

    const int row0 = tid >> 2, seg = tid & 3;

    auto issue = [&](int it) {
        if (it < KIT) {
            const int k0 = it * BK;
            const uint32_t st = sbase + (it % NST0) * ST0;
            cp_async16(st + row0 * AROWB + seg * 16,
                       A + (size_t)(bm + row0) * K0PAD + k0 + seg * 8);
            cp_async16(st + (row0 + 64) * AROWB + seg * 16,
                       A + (size_t)(bm + row0 + 64) * K0PAD + k0 + seg * 8);
            const uint32_t sb = st + AT0;
            #pragma unroll
            for (int j = 0; j < 4; ++j)
                cp_async16_ca(sb + (row0 + 64 * j) * AROWB + seg * 16,
                              Bw + (size_t)(row0 + 64 * j) * K0PAD + k0 + seg * 8);
        }
        cp_commit();
    };

    #pragma unroll
    for (int s = 0; s < NST0 - 1; ++s) issue(s);

    uint32_t c[4][8][2];
    #pragma unroll
    for (int i = 0; i < 4; ++i)
        #pragma unroll
        for (int j = 0; j < 8; ++j) { c[i][j][0] = 0u; c[i][j][1] = 0u; }

    const int a_row  = wm + (lane & 15);
    const int a_koff = (lane >> 4) * 8;
    const int b_row  = wn + (lane & 7) + ((lane >> 4) << 3);
    const int b_koff = (lane & 8);

    for (int i = 0; i < KIT; ++i) {
        cp_wait<NST0 - 2>();
        __syncthreads();
        issue(i + NST0 - 1);

        const uint32_t sa = sbase + (i % NST0) * ST0;
        const uint32_t sb = sa + AT0;

        #pragma unroll
        for (int kk = 0; kk < 2; ++kk) {
            uint32_t a[4][4], b[4][4];
            #pragma unroll
            for (int mt = 0; mt < 4; ++mt)
                ldsm_x4(a[mt], sa + (a_row + mt * 16) * AROWB + (kk * 16 + a_koff) * 2);
            #pragma unroll
            for (int nt = 0; nt < 4; ++nt)
                ldsm_x4(b[nt], sb + (b_row + nt * 16) * AROWB + (kk * 16 + b_koff) * 2);
            #pragma unroll
            for (int mt = 0; mt < 4; ++mt)
                #pragma unroll
                for (int nt = 0; nt < 4; ++nt) {
                    mma_f16(c[mt][2 * nt],     a[mt], b[nt][0], b[nt][1]);
                    mma_f16(c[mt][2 * nt + 1], a[mt], b[nt][2], b[nt][3]);
                }
        }
    }

    const __half2 z2 = __float2half2_rn(0.0f);
    #pragma unroll
    for (int mt = 0; mt < 4; ++mt) {
        const size_t r0 = (size_t)bm + wm + mt * 16 + (lane >> 2);
        #pragma unroll
        for (int j = 0; j < 8; ++j) {
            const int col = bn + wn + j * 8 + 2 * (lane & 3);
            const float2 bf = *reinterpret_cast<const float2*>(bias + col);
            const __half2 bb = __floats2half2_rn(bf.x, bf.y);
            __half2 lo = *reinterpret_cast<__half2*>(&c[mt][j][0]);
            __half2 hi = *reinterpret_cast<__half2*>(&c[mt][j][1]);
            lo = __hmax2(__hadd2(lo, bb), z2);
            hi = __hmax2(__hadd2(hi, bb), z2);
            *reinterpret_cast<__half2*>(g_h1 + r0 * 1024 + col)       = lo;
            *reinterpret_cast<__half2*>(g_h1 + (r0 + 8) * 1024 + col) = hi;
        }
    }
}

// ---------------------------------------------------------------------------
// Fused layers 1+2+head. Grid = 128 CTAs x 256 threads.
#define AT1      (128 * AROWB)             // 10240
#define BT1      (512 * AROWB)             // 40960
#define ST1      (AT1 + BT1)               // 51200
#define NST1     4
#define PIPE1    (NST1 * ST1)              // 204800

#define H2PITCH  520                       // halves (512 + 8 pad)
#define H2BYTES  (128 * H2PITCH * 2)       // 133120
#define P2OFF    H2BYTES
#define BT2      (256 * AROWB)             // 20480
#define NST2     3
#define FUSE_SMEM 204800
#define H3PITCH  264

__global__ __launch_bounds__(256, 1)
void gemm12_head(const float* __restrict__ b1,
                 const float* __restrict__ b2,
                 const float* __restrict__ Wout,
                 const float* __restrict__ bout,
                 float* __restrict__ out) {
    extern __shared__ char smem[];
    const uint32_t sbase = smem_to_u32(smem);
    __half* s_h2 = reinterpret_cast<__half*>(smem);
    __half* s_h3 = reinterpret_cast<__half*>(smem);

    const int tid = threadIdx.x;
    const int warp = tid >> 5, lane = tid & 31;
    const int bm = blockIdx.x * 128;
    const __half2 z2 = __float2half2_rn(0.0f);

    // ---- Phase 1: layer 1 (K=1024, N=512), warp 64x128, f16 acc ----
    {
        const int wm = (warp & 1) * 64, wn = (warp >> 1) * 128;
        const int KIT = 1024 / BK;   // 32
        const int row0 = tid >> 2, seg = tid & 3;

        auto issue = [&](int it) {
            if (it < KIT) {
                const int k0 = it * BK;
                const uint32_t st = sbase + (it % NST1) * ST1;
                cp_async16(st + row0 * AROWB + seg * 16,
                           g_h1 + (size_t)(bm + row0) * 1024 + k0 + seg * 8);
                cp_async16(st + (row0 + 64) * AROWB + seg * 16,
                           g_h1 + (size_t)(bm + row0 + 64) * 1024 + k0 + seg * 8);
                const uint32_t sb = st + AT1;
                #pragma unroll
                for (int j = 0; j < 8; ++j)
                    cp_async16(sb + (row0 + 64 * j) * AROWB + seg * 16,
                               g_W1t + (size_t)(row0 + 64 * j) * 1024 + k0 + seg * 8);
            }
            cp_commit();
        };

        #pragma unroll
        for (int s = 0; s < NST1 - 1; ++s) issue(s);

        uint32_t c[4][16][2];
        #pragma unroll
        for (int i = 0; i < 4; ++i)
            #pragma unroll
            for (int j = 0; j < 16; ++j) { c[i][j][0] = 0u; c[i][j][1] = 0u; }

        const int a_row  = wm + (lane & 15);
        const int a_koff = (lane >> 4) * 8;
        const int b_row  = wn + (lane & 7) + ((lane >> 4) << 3);
        const int b_koff = (lane & 8);

        for (int i = 0; i < KIT; ++i) {
            cp_wait<NST1 - 2>();
            __syncthreads();
            issue(i + NST1 - 1);

            const uint32_t sa = sbase + (i % NST1) * ST1;
            const uint32_t sb = sa + AT1;

            #pragma unroll
            for (int kk = 0; kk < 2; ++kk) {
                uint32_t a[4][4], b[8][4];
                #pragma unroll
                for (int mt = 0; mt < 4; ++mt)
                    ldsm_x4(a[mt], sa + (a_row + mt * 16) * AROWB + (kk * 16 + a_koff) * 2);
                #pragma unroll
                for (int nt = 0; nt < 8; ++nt)
                    ldsm_x4(b[nt], sb + (b_row + nt * 16) * AROWB + (kk * 16 + b_koff) * 2);
                #pragma unroll
                for (int mt = 0; mt < 4; ++mt)
                    #pragma unroll
                    for (int nt = 0; nt < 8; ++nt) {
                        mma_f16(c[mt][2 * nt],     a[mt], b[nt][0], b[nt][1]);
                        mma_f16(c[mt][2 * nt + 1], a[mt], b[nt][2], b[nt][3]);
                    }
            }
        }
        __syncthreads();   // pipeline dead; safe to overwrite with h2

        #pragma unroll
        for (int mt = 0; mt < 4; ++mt) {
            const int r0 = wm + mt * 16 + (lane >> 2);
            #pragma unroll
            for (int nt = 0; nt < 16; ++nt) {
                const int col = wn + nt * 8 + 2 * (lane & 3);
                const float2 bf = *reinterpret_cast<const float2*>(b1 + col);
                const __half2 bb = __floats2half2_rn(bf.x, bf.y);
                __half2 lo = *reinterpret_cast<__half2*>(&c[mt][nt][0]);
                __half2 hi = *reinterpret_cast<__half2*>(&c[mt][nt][1]);
                lo = __hmax2(__hadd2(lo, bb), z2);
                hi = __hmax2(__hadd2(hi, bb), z2);
                *reinterpret_cast<__half2*>(s_h2 + r0 * H2PITCH + col)       = lo;
                *reinterpret_cast<__half2*>(s_h2 + (r0 + 8) * H2PITCH + col) = hi;
            }
        }
    }
    __syncthreads();

    // ---- Phase 2: layer 2 (K=512, N=256), warp 64x64, f16 acc ----
    uint32_t c2[4][8][2];
    {
        const int wm = (warp & 1) * 64, wn = (warp >> 1) * 64;
        const int KIT = 512 / BK;   // 16
        const int row0 = tid >> 2, seg = tid & 3;

        auto issueB = [&](int it) {
            if (it < KIT) {
                const int k0 = it * BK;
                const uint32_t st = sbase + P2OFF + (it % NST2) * BT2;
                #pragma unroll
                for (int j = 0; j < 4; ++j)
                    cp_async16(st + (row0 + 64 * j) * AROWB + seg * 16,
                               g_W2t + (size_t)(row0 + 64 * j) * 512 + k0 + seg * 8);
            }
            cp_commit();
        };
        #pragma unroll
        for (int s = 0; s < NST2 - 1; ++s) issueB(s);

        #pragma unroll
        for (int i = 0; i < 4; ++i)
            #pragma unroll
            for (int j = 0; j < 8; ++j) { c2[i][j][0] = 0u; c2[i][j][1] = 0u; }

        const int a_row  = wm + (lane & 15);
        const int a_koff = (lane >> 4) * 8;
        const int b_row  = wn + (lane & 7) + ((lane >> 4) << 3);
        const int b_koff = (lane & 8);

        for (int i = 0; i < KIT; ++i) {
            cp_wait<NST2 - 2>();
            __syncthreads();
            issueB(i + NST2 - 1);

            const uint32_t sb = sbase + P2OFF + (i % NST2) * BT2;

            #pragma unroll
            for (int kk = 0; kk < 2; ++kk) {
                uint32_t a[4][4], b[4][4];
                #pragma unroll
                for (int mt = 0; mt < 4; ++mt)
                    ldsm_x4(a[mt], sbase + (a_row + mt * 16) * (H2PITCH * 2)
                                       + (i * 32 + kk * 16 + a_koff) * 2);
                #pragma unroll
                for (int nt = 0; nt < 4; ++nt)
                    ldsm_x4(b[nt], sb + (b_row + nt * 16) * AROWB + (kk * 16 + b_koff) * 2);
                #pragma unroll
                for (int mt = 0; mt < 4; ++mt)
                    #pragma unroll
                    for (int nt = 0; nt < 4; ++nt) {
                        mma_f16(c2[mt][2 * nt],     a[mt], b[nt][0], b[nt][1]);
                        mma_f16(c2[mt][2 * nt + 1], a[mt], b[nt][2], b[nt][3]);
                    }
            }
        }
    }
    __syncthreads();   // h2 dead; reuse offset 0 for h3

    // ---- Phase 3: h3 -> smem, head ----
    {
        const int wm = (warp & 1) * 64, wn = (warp >> 1) * 64;
        #pragma unroll
        for (int mt = 0; mt < 4; ++mt) {
            const int r0 = wm + mt * 16 + (lane >> 2);
            #pragma unroll
            for (int j = 0; j < 8; ++j) {
                const int col = wn + j * 8 + 2 * (lane & 3);
                const float2 bf = *reinterpret_cast<const float2*>(b2 + col);
                const __half2 bb = __floats2half2_rn(bf.x, bf.y);
                __half2 lo = *reinterpret_cast<__half2*>(&c2[mt][j][0]);
                __half2 hi = *reinterpret_cast<__half2*>(&c2[mt][j][1]);
                lo = __hmax2(__hadd2(lo, bb), z2);
                hi = __hmax2(__hadd2(hi, bb), z2);
                *reinterpret_cast<__half2*>(s_h3 + r0 * H3PITCH + col)       = lo;
                *reinterpret_cast<__half2*>(s_h3 + (r0 + 8) * H3PITCH + col) = hi;
            }
        }
    }
    __syncthreads();

    float wreg[8];
    #pragma unroll
    for (int j = 0; j < 8; ++j) wreg[j] = __ldg(Wout + j * 32 + lane);
    const float bo = __ldg(bout);

    #pragma unroll 1
    for (int t = 0; t < 16; ++t) {
        const int row = warp * 16 + t;
        float acc = 0.0f;
        #pragma unroll
        for (int j = 0; j < 8; ++j)
            acc += __half2float(s_h3[row * H3PITCH + j * 32 + lane]) * wreg[j];
        #pragma unroll
        for (int o = 16; o; o >>= 1) acc += __shfl_xor_sync(0xffffffffu, acc, o);
        if (lane == 0) {
            float logit = acc + bo + g_logit0[bm + row];
            out[bm + row] = 1.0f / (1.0f + expf(-logit));
        }
    }
}

// ---------------------------------------------------------------------------
extern "C" void kernel_launch(void* const* d_in, const int* in_sizes, int n_in,
                              void* d_out, int out_size) {
    const int*   xs   = (const int*)  d_in[0];
    const float* xd   = (const float*)d_in[1];
    const float* emb  = (const float*)d_in[2];
    const float* lin  = (const float*)d_in[3];
    const float* W0   = (const float*)d_in[4];
    const float* b0   = (const float*)d_in[5];
    const float* W1   = (const float*)d_in[6];
    const float* b1   = (const float*)d_in[7];
    const float* W2   = (const float*)d_in[8];
    const float* b2   = (const float*)d_in[9];
    const float* Wout = (const float*)d_in[10];
    const float* bout = (const float*)d_in[11];
    float* out = (float*)d_out;

    static bool attr_done = false;
    if (!attr_done) {
        cudaFuncSetAttribute(gemm_mma0,
                             cudaFuncAttributeMaxDynamicSharedMemorySize, GEMM0_SMEM);
        cudaFuncSetAttribute(gemm12_head,
                             cudaFuncAttributeMaxDynamicSharedMemorySize, FUSE_SMEM);
        attr_done = true;
    }

    prepare_kernel<<<NB_PREP, 256>>>(xs, xd, emb, lin, W0);
    gemm_mma0<<<NB_GEMM0, 256, GEMM0_SMEM>>>(b0, W1, W2);
    gemm12_head<<<128, 256, FUSE_SMEM>>>(b1, b2, Wout, bout, out);
}